// round 7
// baseline (speedup 1.0000x reference)
#include <cuda_runtime.h>
#include <stdint.h>

#define MAX_NODES 100000
#define MAX_EDGES 1600000
#define D 128

typedef unsigned long long ull;

// ---- device scratch ----
__device__ __align__(256) int  g_deg[MAX_NODES];
__device__ __align__(256) int  g_off[MAX_NODES + 1];
__device__ __align__(256) int  g_cur[MAX_NODES];
__device__ __align__(256) int  g_bsum[128];
__device__ __align__(256) int  g_bsumx[128];
__device__ __align__(256) ull  g_pairs[MAX_EDGES];   // (wt<<32 | src)

// ---------------------------------------------------------------------------
__global__ void zero_deg_kernel(int n) {
    int i = blockIdx.x * blockDim.x + threadIdx.x;
    if (i < n) g_deg[i] = 0;
}

__global__ void count_kernel(const int* __restrict__ ei, int E, int N) {
    int e = blockIdx.x * blockDim.x + threadIdx.x;
    if (e < E) {
        int dst = ei[E + e];
        if ((unsigned)dst < (unsigned)N) atomicAdd(&g_deg[dst], 1);
    }
}

__global__ __launch_bounds__(1024) void scan_blocks_kernel(int n) {
    __shared__ int warp_sums[32];
    const int tid  = threadIdx.x;
    const int lane = tid & 31;
    const int wid  = tid >> 5;
    const int i    = blockIdx.x * 1024 + tid;

    int v = (i < n) ? g_deg[i] : 0;
    int incl = v;
    #pragma unroll
    for (int d = 1; d < 32; d <<= 1) {
        int t = __shfl_up_sync(0xFFFFFFFFu, incl, d);
        if (lane >= d) incl += t;
    }
    if (lane == 31) warp_sums[wid] = incl;
    __syncthreads();
    if (wid == 0) {
        int wv = warp_sums[lane];
        #pragma unroll
        for (int d = 1; d < 32; d <<= 1) {
            int t = __shfl_up_sync(0xFFFFFFFFu, wv, d);
            if (lane >= d) wv += t;
        }
        warp_sums[lane] = wv;
    }
    __syncthreads();
    int base = (wid > 0) ? warp_sums[wid - 1] : 0;
    if (i < n) g_off[i] = base + incl - v;
    if (tid == 1023) g_bsum[blockIdx.x] = warp_sums[31];
}

__global__ void scan_bsum_kernel(int nb, int n) {
    __shared__ int wsum[4];
    const int t    = threadIdx.x;
    const int lane = t & 31;
    const int wid  = t >> 5;
    int v = (t < nb) ? g_bsum[t] : 0;
    int incl = v;
    #pragma unroll
    for (int d = 1; d < 32; d <<= 1) {
        int s = __shfl_up_sync(0xFFFFFFFFu, incl, d);
        if (lane >= d) incl += s;
    }
    if (lane == 31) wsum[wid] = incl;
    __syncthreads();
    int base = 0;
    #pragma unroll
    for (int j = 0; j < 4; j++) base += (j < wid) ? wsum[j] : 0;
    if (t < nb) g_bsumx[t] = base + incl - v;
    if (t == 0) g_off[n] = wsum[0] + wsum[1] + wsum[2] + wsum[3];
}

__global__ __launch_bounds__(1024) void scan_add_kernel(int n) {
    int i = blockIdx.x * 1024 + threadIdx.x;
    if (i < n) {
        int val = g_off[i] + g_bsumx[blockIdx.x];
        g_off[i] = val;
        g_cur[i] = val;
    }
}

__global__ void fill_kernel(const int* __restrict__ ei,
                            const float* __restrict__ ew, int E, int N) {
    int e = blockIdx.x * blockDim.x + threadIdx.x;
    if (e < E) {
        int src = ei[e];
        int dst = ei[E + e];
        if ((unsigned)dst < (unsigned)N && (unsigned)src < (unsigned)N) {
            int pos = atomicAdd(&g_cur[dst], 1);
            ull p = ((ull)__float_as_uint(ew[e]) << 32) | (unsigned)src;
            g_pairs[pos] = p;
        }
    }
}

// ============================================================================
// Fused aggregate + GEMM.
// Block = 512 threads, owns 128 nodes.
// Phase 1: warp w aggregates nodes w*8..w*8+7 (register float4 accum, 4-deep
//          gather unroll), stores rows into smem xs[m][k] ([128][132] padded).
// Phase 2: out[m][n] = sum_k xs[m][k]*W[n][k] + b[n] with f32x2 packed FMAs.
//          Per-thread 4(M) x 8(N); W staged k-major in ws[32][132] chunks.
// ============================================================================

__device__ __forceinline__ ull pack_dup(float a) {
    ull r;
    unsigned int u = __float_as_uint(a);
    asm("mov.b64 %0, {%1, %2};" : "=l"(r) : "r"(u), "r"(u));
    return r;
}

__device__ __forceinline__ void fma_x2(ull& acc, ull a, ull w) {
    asm("fma.rn.f32x2 %0, %1, %2, %0;" : "+l"(acc) : "l"(a), "l"(w));
}

#define SM_FLOATS (128 * 132 + 32 * 132)

__global__ __launch_bounds__(512, 2)
void agg_gemm_kernel(const float* __restrict__ x, const float* __restrict__ W,
                     const float* __restrict__ b, float* __restrict__ out, int M) {
    extern __shared__ __align__(16) float sm[];
    float* xs = sm;               // [128][132]  xs[m][k]
    float* ws = sm + 128 * 132;   // [32][132]   ws[k][n]

    const int tid  = threadIdx.x;
    const int lane = tid & 31;
    const int w    = tid >> 5;    // warp 0..15
    const int mb   = blockIdx.x * 128;

    // ---- Phase 1: aggregate 8 nodes per warp into xs ----
    #pragma unroll 1
    for (int j = 0; j < 8; j++) {
        int nloc = w * 8 + j;
        int node = mb + nloc;
        float4 a0 = make_float4(0.f, 0.f, 0.f, 0.f);
        float4 a1 = make_float4(0.f, 0.f, 0.f, 0.f);
        float4 a2 = make_float4(0.f, 0.f, 0.f, 0.f);
        float4 a3 = make_float4(0.f, 0.f, 0.f, 0.f);
        if (node < M) {
            int i   = g_off[node];
            int end = g_off[node + 1];
            for (; i + 4 <= end; i += 4) {
                ull p0 = g_pairs[i],     p1 = g_pairs[i + 1];
                ull p2 = g_pairs[i + 2], p3 = g_pairs[i + 3];
                int   s0 = (int)(unsigned)p0, s1 = (int)(unsigned)p1;
                int   s2 = (int)(unsigned)p2, s3 = (int)(unsigned)p3;
                float w0 = __uint_as_float((unsigned)(p0 >> 32));
                float w1 = __uint_as_float((unsigned)(p1 >> 32));
                float w2 = __uint_as_float((unsigned)(p2 >> 32));
                float w3 = __uint_as_float((unsigned)(p3 >> 32));
                float4 v0 = *((const float4*)(x + (size_t)s0 * D) + lane);
                float4 v1 = *((const float4*)(x + (size_t)s1 * D) + lane);
                float4 v2 = *((const float4*)(x + (size_t)s2 * D) + lane);
                float4 v3 = *((const float4*)(x + (size_t)s3 * D) + lane);
                a0.x += w0 * v0.x; a0.y += w0 * v0.y; a0.z += w0 * v0.z; a0.w += w0 * v0.w;
                a1.x += w1 * v1.x; a1.y += w1 * v1.y; a1.z += w1 * v1.z; a1.w += w1 * v1.w;
                a2.x += w2 * v2.x; a2.y += w2 * v2.y; a2.z += w2 * v2.z; a2.w += w2 * v2.w;
                a3.x += w3 * v3.x; a3.y += w3 * v3.y; a3.z += w3 * v3.z; a3.w += w3 * v3.w;
            }
            for (; i < end; i++) {
                ull p = g_pairs[i];
                int   s = (int)(unsigned)p;
                float wt = __uint_as_float((unsigned)(p >> 32));
                float4 v = *((const float4*)(x + (size_t)s * D) + lane);
                a0.x += wt * v.x; a0.y += wt * v.y; a0.z += wt * v.z; a0.w += wt * v.w;
            }
        }
        float4 r = make_float4(a0.x + a1.x + a2.x + a3.x,
                               a0.y + a1.y + a2.y + a3.y,
                               a0.z + a1.z + a2.z + a3.z,
                               a0.w + a1.w + a2.w + a3.w);
        *(float4*)&xs[nloc * 132 + lane * 4] = r;   // 16B-aligned (528B rows)
    }
    __syncthreads();

    // ---- Phase 2: GEMM from smem ----
    const int tn = tid & 15;      // n0 = tn*8
    const int tm = tid >> 4;      // m0 = tm*4  (0..31)

    ull acc[4][4];
    #pragma unroll
    for (int i = 0; i < 4; i++)
        #pragma unroll
        for (int j = 0; j < 4; j++) acc[i][j] = 0ULL;

    for (int kb = 0; kb < 128; kb += 32) {
        #pragma unroll
        for (int idx = tid; idx < 128 * 32; idx += 512) {
            int kk = idx & 31, nn = idx >> 5;
            ws[kk * 132 + nn] = W[nn * 128 + kb + kk];
        }
        __syncthreads();
        #pragma unroll
        for (int k = 0; k < 32; k++) {
            float av0 = xs[(tm * 4 + 0) * 132 + kb + k];
            float av1 = xs[(tm * 4 + 1) * 132 + kb + k];
            float av2 = xs[(tm * 4 + 2) * 132 + kb + k];
            float av3 = xs[(tm * 4 + 3) * 132 + kb + k];
            const ull* wp = (const ull*)&ws[k * 132 + tn * 8];
            ull w0 = wp[0], w1 = wp[1], w2 = wp[2], w3 = wp[3];
            ull d0 = pack_dup(av0), d1 = pack_dup(av1);
            ull d2 = pack_dup(av2), d3 = pack_dup(av3);
            fma_x2(acc[0][0], d0, w0); fma_x2(acc[0][1], d0, w1);
            fma_x2(acc[0][2], d0, w2); fma_x2(acc[0][3], d0, w3);
            fma_x2(acc[1][0], d1, w0); fma_x2(acc[1][1], d1, w1);
            fma_x2(acc[1][2], d1, w2); fma_x2(acc[1][3], d1, w3);
            fma_x2(acc[2][0], d2, w0); fma_x2(acc[2][1], d2, w1);
            fma_x2(acc[2][2], d2, w2); fma_x2(acc[2][3], d2, w3);
            fma_x2(acc[3][0], d3, w0); fma_x2(acc[3][1], d3, w1);
            fma_x2(acc[3][2], d3, w2); fma_x2(acc[3][3], d3, w3);
        }
        __syncthreads();
    }

    float bias[8];
    #pragma unroll
    for (int j = 0; j < 8; j++) bias[j] = b[tn * 8 + j];
    #pragma unroll
    for (int i = 0; i < 4; i++) {
        int row = mb + tm * 4 + i;
        if (row < M) {
            float r[8];
            #pragma unroll
            for (int j = 0; j < 4; j++) {
                unsigned int lo, hi;
                asm("mov.b64 {%0, %1}, %2;" : "=r"(lo), "=r"(hi) : "l"(acc[i][j]));
                r[j * 2]     = __uint_as_float(lo);
                r[j * 2 + 1] = __uint_as_float(hi);
            }
            float4 o0 = make_float4(r[0] + bias[0], r[1] + bias[1],
                                    r[2] + bias[2], r[3] + bias[3]);
            float4 o1 = make_float4(r[4] + bias[4], r[5] + bias[5],
                                    r[6] + bias[6], r[7] + bias[7]);
            *(float4*)(out + (size_t)row * 128 + tn * 8)     = o0;
            *(float4*)(out + (size_t)row * 128 + tn * 8 + 4) = o1;
        }
    }
}

// ---------------------------------------------------------------------------
extern "C" void kernel_launch(void* const* d_in, const int* in_sizes, int n_in,
                              void* d_out, int out_size) {
    const float* x  = (const float*)d_in[0];
    const int*   ei = (const int*)d_in[1];     // int32 edge_index [2, E]
    const float* ew = (const float*)d_in[2];
    const float* W  = (const float*)d_in[3];
    const float* b  = (const float*)d_in[4];
    float*       out = (float*)d_out;

    int N = in_sizes[0] / D;      // 100000
    int E = in_sizes[2];          // 1600000
    int nb = (N + 1023) / 1024;   // 98

    zero_deg_kernel<<<(N + 255) / 256, 256>>>(N);
    count_kernel<<<(E + 255) / 256, 256>>>(ei, E, N);
    scan_blocks_kernel<<<nb, 1024>>>(N);
    scan_bsum_kernel<<<1, 128>>>(nb, N);
    scan_add_kernel<<<nb, 1024>>>(N);
    fill_kernel<<<(E + 255) / 256, 256>>>(ei, ew, E, N);

    cudaFuncSetAttribute(agg_gemm_kernel,
                         cudaFuncAttributeMaxDynamicSharedMemorySize,
                         SM_FLOATS * sizeof(float));
    agg_gemm_kernel<<<(N + 127) / 128, 512, SM_FLOATS * sizeof(float)>>>(
        x, W, b, out, N);
}

// round 8
// speedup vs baseline: 1.0638x; 1.0638x over previous
#include <cuda_runtime.h>
#include <stdint.h>

#define MAX_NODES 100000
#define MAX_EDGES 1600000
#define D 128

typedef unsigned long long ull;

// ---- device scratch ----
__device__ __align__(256) int  g_deg[MAX_NODES];
__device__ __align__(256) int  g_off[MAX_NODES + 1];
__device__ __align__(256) int  g_cur[MAX_NODES];
__device__ __align__(256) int  g_bsum[128];
__device__ __align__(256) int  g_bsumx[128];
__device__ __align__(256) ull  g_pairs[MAX_EDGES];   // (wt<<32 | src)
__device__ __align__(256) float g_agg[(size_t)MAX_NODES * D];

// ---------------------------------------------------------------------------
__global__ void zero_deg_kernel(int n) {
    int i = blockIdx.x * blockDim.x + threadIdx.x;
    if (i < n) g_deg[i] = 0;
}

__global__ void count_kernel(const int* __restrict__ ei, int E, int N) {
    int e = blockIdx.x * blockDim.x + threadIdx.x;
    if (e < E) {
        int dst = ei[E + e];
        if ((unsigned)dst < (unsigned)N) atomicAdd(&g_deg[dst], 1);
    }
}

__global__ __launch_bounds__(1024) void scan_blocks_kernel(int n) {
    __shared__ int warp_sums[32];
    const int tid  = threadIdx.x;
    const int lane = tid & 31;
    const int wid  = tid >> 5;
    const int i    = blockIdx.x * 1024 + tid;

    int v = (i < n) ? g_deg[i] : 0;
    int incl = v;
    #pragma unroll
    for (int d = 1; d < 32; d <<= 1) {
        int t = __shfl_up_sync(0xFFFFFFFFu, incl, d);
        if (lane >= d) incl += t;
    }
    if (lane == 31) warp_sums[wid] = incl;
    __syncthreads();
    if (wid == 0) {
        int wv = warp_sums[lane];
        #pragma unroll
        for (int d = 1; d < 32; d <<= 1) {
            int t = __shfl_up_sync(0xFFFFFFFFu, wv, d);
            if (lane >= d) wv += t;
        }
        warp_sums[lane] = wv;
    }
    __syncthreads();
    int base = (wid > 0) ? warp_sums[wid - 1] : 0;
    if (i < n) g_off[i] = base + incl - v;
    if (tid == 1023) g_bsum[blockIdx.x] = warp_sums[31];
}

__global__ void scan_bsum_kernel(int nb, int n) {
    __shared__ int wsum[4];
    const int t    = threadIdx.x;
    const int lane = t & 31;
    const int wid  = t >> 5;
    int v = (t < nb) ? g_bsum[t] : 0;
    int incl = v;
    #pragma unroll
    for (int d = 1; d < 32; d <<= 1) {
        int s = __shfl_up_sync(0xFFFFFFFFu, incl, d);
        if (lane >= d) incl += s;
    }
    if (lane == 31) wsum[wid] = incl;
    __syncthreads();
    int base = 0;
    #pragma unroll
    for (int j = 0; j < 4; j++) base += (j < wid) ? wsum[j] : 0;
    if (t < nb) g_bsumx[t] = base + incl - v;
    if (t == 0) g_off[n] = wsum[0] + wsum[1] + wsum[2] + wsum[3];
}

__global__ __launch_bounds__(1024) void scan_add_kernel(int n) {
    int i = blockIdx.x * 1024 + threadIdx.x;
    if (i < n) {
        int val = g_off[i] + g_bsumx[blockIdx.x];
        g_off[i] = val;
        g_cur[i] = val;
    }
}

__global__ void fill_kernel(const int* __restrict__ ei,
                            const float* __restrict__ ew, int E, int N) {
    int e = blockIdx.x * blockDim.x + threadIdx.x;
    if (e < E) {
        int src = ei[e];
        int dst = ei[E + e];
        if ((unsigned)dst < (unsigned)N && (unsigned)src < (unsigned)N) {
            int pos = atomicAdd(&g_cur[dst], 1);
            ull p = ((ull)__float_as_uint(ew[e]) << 32) | (unsigned)src;
            g_pairs[pos] = p;
        }
    }
}

// One warp per node; 8-deep unrolled gather for MLP.
__global__ void aggregate_kernel(const float* __restrict__ x, int n) {
    int gw   = (blockIdx.x * blockDim.x + threadIdx.x) >> 5;
    int lane = threadIdx.x & 31;
    if (gw >= n) return;
    int i   = g_off[gw];
    int end = g_off[gw + 1];
    float4 a0 = make_float4(0.f, 0.f, 0.f, 0.f);
    float4 a1 = make_float4(0.f, 0.f, 0.f, 0.f);
    float4 a2 = make_float4(0.f, 0.f, 0.f, 0.f);
    float4 a3 = make_float4(0.f, 0.f, 0.f, 0.f);
    for (; i + 8 <= end; i += 8) {
        ull p0 = g_pairs[i],     p1 = g_pairs[i + 1];
        ull p2 = g_pairs[i + 2], p3 = g_pairs[i + 3];
        ull p4 = g_pairs[i + 4], p5 = g_pairs[i + 5];
        ull p6 = g_pairs[i + 6], p7 = g_pairs[i + 7];
        const float4* q0 = (const float4*)(x + (size_t)(unsigned)(unsigned int)p0 * D) + lane;
        const float4* q1 = (const float4*)(x + (size_t)(unsigned)(unsigned int)p1 * D) + lane;
        const float4* q2 = (const float4*)(x + (size_t)(unsigned)(unsigned int)p2 * D) + lane;
        const float4* q3 = (const float4*)(x + (size_t)(unsigned)(unsigned int)p3 * D) + lane;
        const float4* q4 = (const float4*)(x + (size_t)(unsigned)(unsigned int)p4 * D) + lane;
        const float4* q5 = (const float4*)(x + (size_t)(unsigned)(unsigned int)p5 * D) + lane;
        const float4* q6 = (const float4*)(x + (size_t)(unsigned)(unsigned int)p6 * D) + lane;
        const float4* q7 = (const float4*)(x + (size_t)(unsigned)(unsigned int)p7 * D) + lane;
        float4 v0 = *q0, v1 = *q1, v2 = *q2, v3 = *q3;
        float4 v4 = *q4, v5 = *q5, v6 = *q6, v7 = *q7;
        float w0 = __uint_as_float((unsigned)(p0 >> 32));
        float w1 = __uint_as_float((unsigned)(p1 >> 32));
        float w2 = __uint_as_float((unsigned)(p2 >> 32));
        float w3 = __uint_as_float((unsigned)(p3 >> 32));
        float w4 = __uint_as_float((unsigned)(p4 >> 32));
        float w5 = __uint_as_float((unsigned)(p5 >> 32));
        float w6 = __uint_as_float((unsigned)(p6 >> 32));
        float w7 = __uint_as_float((unsigned)(p7 >> 32));
        a0.x += w0 * v0.x; a0.y += w0 * v0.y; a0.z += w0 * v0.z; a0.w += w0 * v0.w;
        a1.x += w1 * v1.x; a1.y += w1 * v1.y; a1.z += w1 * v1.z; a1.w += w1 * v1.w;
        a2.x += w2 * v2.x; a2.y += w2 * v2.y; a2.z += w2 * v2.z; a2.w += w2 * v2.w;
        a3.x += w3 * v3.x; a3.y += w3 * v3.y; a3.z += w3 * v3.z; a3.w += w3 * v3.w;
        a0.x += w4 * v4.x; a0.y += w4 * v4.y; a0.z += w4 * v4.z; a0.w += w4 * v4.w;
        a1.x += w5 * v5.x; a1.y += w5 * v5.y; a1.z += w5 * v5.z; a1.w += w5 * v5.w;
        a2.x += w6 * v6.x; a2.y += w6 * v6.y; a2.z += w6 * v6.z; a2.w += w6 * v6.w;
        a3.x += w7 * v7.x; a3.y += w7 * v7.y; a3.z += w7 * v7.z; a3.w += w7 * v7.w;
    }
    for (; i + 2 <= end; i += 2) {
        ull p0 = g_pairs[i], p1 = g_pairs[i + 1];
        float4 v0 = *((const float4*)(x + (size_t)(unsigned)(unsigned int)p0 * D) + lane);
        float4 v1 = *((const float4*)(x + (size_t)(unsigned)(unsigned int)p1 * D) + lane);
        float w0 = __uint_as_float((unsigned)(p0 >> 32));
        float w1 = __uint_as_float((unsigned)(p1 >> 32));
        a0.x += w0 * v0.x; a0.y += w0 * v0.y; a0.z += w0 * v0.z; a0.w += w0 * v0.w;
        a1.x += w1 * v1.x; a1.y += w1 * v1.y; a1.z += w1 * v1.z; a1.w += w1 * v1.w;
    }
    if (i < end) {
        ull p = g_pairs[i];
        float wt = __uint_as_float((unsigned)(p >> 32));
        float4 v = *((const float4*)(x + (size_t)(unsigned)(unsigned int)p * D) + lane);
        a0.x += wt * v.x; a0.y += wt * v.y; a0.z += wt * v.z; a0.w += wt * v.w;
    }
    float4 r = make_float4(a0.x + a1.x + a2.x + a3.x,
                           a0.y + a1.y + a2.y + a3.y,
                           a0.z + a1.z + a2.z + a3.z,
                           a0.w + a1.w + a2.w + a3.w);
    *((float4*)(g_agg + (size_t)gw * D) + lane) = r;
}

// ============================================================================
// SIMT GEMM with packed f32x2 FMAs. out[m][n] = sum_k agg[m][k]*W[n][k] + b[n].
// 256 thr, tile 128(M) x 128(N), per-thread 8x8 (8 x 4 f32x2 pairs),
// K-chunks of 32. Tiles k-major [32][132].
// ============================================================================

__device__ __forceinline__ ull pack_dup(float a) {
    ull r;
    unsigned int u = __float_as_uint(a);
    asm("mov.b64 %0, {%1, %2};" : "=l"(r) : "r"(u), "r"(u));
    return r;
}

__device__ __forceinline__ void fma_x2(ull& acc, ull a, ull w) {
    asm("fma.rn.f32x2 %0, %1, %2, %0;" : "+l"(acc) : "l"(a), "l"(w));
}

__global__ __launch_bounds__(256) void gemm_kernel(const float* __restrict__ W,
                                                   const float* __restrict__ b,
                                                   float* __restrict__ out, int M) {
    __shared__ __align__(16) float ws[32][132];
    __shared__ __align__(16) float xs[32][132];
    const int tid = threadIdx.x;
    const int tn  = tid & 15;
    const int tm  = tid >> 4;
    const int mb  = blockIdx.x * 128;

    ull acc[8][4];
    #pragma unroll
    for (int i = 0; i < 8; i++)
        #pragma unroll
        for (int j = 0; j < 4; j++) acc[i][j] = 0ULL;

    for (int kb = 0; kb < 128; kb += 32) {
        #pragma unroll
        for (int idx = tid; idx < 128 * 32; idx += 256) {
            int kk = idx & 31, nn = idx >> 5;
            ws[kk][nn] = W[nn * 128 + kb + kk];
        }
        #pragma unroll
        for (int idx = tid; idx < 128 * 32; idx += 256) {
            int kk = idx & 31, mm = idx >> 5;
            int row = mb + mm;
            xs[kk][mm] = (row < M) ? g_agg[(size_t)row * 128 + kb + kk] : 0.f;
        }
        __syncthreads();
        #pragma unroll
        for (int k = 0; k < 32; k++) {
            float4 x0 = *(const float4*)&xs[k][tm * 8];
            float4 x1 = *(const float4*)&xs[k][tm * 8 + 4];
            const ull* wp = (const ull*)&ws[k][tn * 8];
            ull w0 = wp[0], w1 = wp[1], w2 = wp[2], w3 = wp[3];
            float av[8] = {x0.x, x0.y, x0.z, x0.w, x1.x, x1.y, x1.z, x1.w};
            #pragma unroll
            for (int i = 0; i < 8; i++) {
                ull ad = pack_dup(av[i]);
                fma_x2(acc[i][0], ad, w0);
                fma_x2(acc[i][1], ad, w1);
                fma_x2(acc[i][2], ad, w2);
                fma_x2(acc[i][3], ad, w3);
            }
        }
        __syncthreads();
    }

    float bias[8];
    #pragma unroll
    for (int j = 0; j < 8; j++) bias[j] = b[tn * 8 + j];
    #pragma unroll
    for (int i = 0; i < 8; i++) {
        int row = mb + tm * 8 + i;
        if (row < M) {
            float r[8];
            #pragma unroll
            for (int j = 0; j < 4; j++) {
                unsigned int lo, hi;
                asm("mov.b64 {%0, %1}, %2;" : "=r"(lo), "=r"(hi) : "l"(acc[i][j]));
                r[j * 2]     = __uint_as_float(lo);
                r[j * 2 + 1] = __uint_as_float(hi);
            }
            float4 o0 = make_float4(r[0] + bias[0], r[1] + bias[1],
                                    r[2] + bias[2], r[3] + bias[3]);
            float4 o1 = make_float4(r[4] + bias[4], r[5] + bias[5],
                                    r[6] + bias[6], r[7] + bias[7]);
            *(float4*)(out + (size_t)row * 128 + tn * 8)     = o0;
            *(float4*)(out + (size_t)row * 128 + tn * 8 + 4) = o1;
        }
    }
}

// ---------------------------------------------------------------------------
extern "C" void kernel_launch(void* const* d_in, const int* in_sizes, int n_in,
                              void* d_out, int out_size) {
    const float* x  = (const float*)d_in[0];
    const int*   ei = (const int*)d_in[1];     // int32 edge_index [2, E]
    const float* ew = (const float*)d_in[2];
    const float* W  = (const float*)d_in[3];
    const float* b  = (const float*)d_in[4];
    float*       out = (float*)d_out;

    int N = in_sizes[0] / D;      // 100000
    int E = in_sizes[2];          // 1600000
    int nb = (N + 1023) / 1024;   // 98

    zero_deg_kernel<<<(N + 255) / 256, 256>>>(N);
    count_kernel<<<(E + 255) / 256, 256>>>(ei, E, N);
    scan_blocks_kernel<<<nb, 1024>>>(N);
    scan_bsum_kernel<<<1, 128>>>(nb, N);
    scan_add_kernel<<<nb, 1024>>>(N);
    fill_kernel<<<(E + 255) / 256, 256>>>(ei, ew, E, N);
    aggregate_kernel<<<((size_t)N * 32 + 255) / 256, 256>>>(x, N);
    gemm_kernel<<<(N + 127) / 128, 256>>>(W, b, out, N);
}

// round 9
// speedup vs baseline: 1.0929x; 1.0273x over previous
#include <cuda_runtime.h>
#include <cuda_fp16.h>
#include <stdint.h>

#define MAX_NODES 100000
#define MAX_EDGES 1600000
#define D 128

typedef unsigned long long ull;

// ---- device scratch ----
__device__ __align__(256) int    g_deg[MAX_NODES];
__device__ __align__(256) int    g_off[MAX_NODES + 1];
__device__ __align__(256) int    g_cur[MAX_NODES];
__device__ __align__(256) int    g_bsum[128];
__device__ __align__(256) int    g_bsumx[128];
__device__ __align__(256) int    g_srcs[MAX_EDGES];
__device__ __align__(256) float  g_wts[MAX_EDGES];
__device__ __align__(256) __half g_x16[(size_t)MAX_NODES * D];
__device__ __align__(256) float  g_agg[(size_t)MAX_NODES * D];

// ---------------------------------------------------------------------------
__global__ void zero_deg_kernel(int n) {
    int i = blockIdx.x * blockDim.x + threadIdx.x;
    if (i < n) g_deg[i] = 0;
}

// fp32 x -> fp16 copy (halves gather traffic; fp32 accumulate keeps error low)
__global__ void convert_x_kernel(const float* __restrict__ x, int total4) {
    int i = blockIdx.x * blockDim.x + threadIdx.x;
    if (i < total4) {
        float4 v = ((const float4*)x)[i];
        __half2* o = (__half2*)g_x16 + i * 2;
        o[0] = __floats2half2_rn(v.x, v.y);
        o[1] = __floats2half2_rn(v.z, v.w);
    }
}

__global__ void count_kernel(const int* __restrict__ ei, int E, int N) {
    int e = blockIdx.x * blockDim.x + threadIdx.x;
    if (e < E) {
        int dst = ei[E + e];
        if ((unsigned)dst < (unsigned)N) atomicAdd(&g_deg[dst], 1);
    }
}

__global__ __launch_bounds__(1024) void scan_blocks_kernel(int n) {
    __shared__ int warp_sums[32];
    const int tid  = threadIdx.x;
    const int lane = tid & 31;
    const int wid  = tid >> 5;
    const int i    = blockIdx.x * 1024 + tid;

    int v = (i < n) ? g_deg[i] : 0;
    int incl = v;
    #pragma unroll
    for (int d = 1; d < 32; d <<= 1) {
        int t = __shfl_up_sync(0xFFFFFFFFu, incl, d);
        if (lane >= d) incl += t;
    }
    if (lane == 31) warp_sums[wid] = incl;
    __syncthreads();
    if (wid == 0) {
        int wv = warp_sums[lane];
        #pragma unroll
        for (int d = 1; d < 32; d <<= 1) {
            int t = __shfl_up_sync(0xFFFFFFFFu, wv, d);
            if (lane >= d) wv += t;
        }
        warp_sums[lane] = wv;
    }
    __syncthreads();
    int base = (wid > 0) ? warp_sums[wid - 1] : 0;
    if (i < n) g_off[i] = base + incl - v;
    if (tid == 1023) g_bsum[blockIdx.x] = warp_sums[31];
}

__global__ void scan_bsum_kernel(int nb, int n) {
    __shared__ int wsum[4];
    const int t    = threadIdx.x;
    const int lane = t & 31;
    const int wid  = t >> 5;
    int v = (t < nb) ? g_bsum[t] : 0;
    int incl = v;
    #pragma unroll
    for (int d = 1; d < 32; d <<= 1) {
        int s = __shfl_up_sync(0xFFFFFFFFu, incl, d);
        if (lane >= d) incl += s;
    }
    if (lane == 31) wsum[wid] = incl;
    __syncthreads();
    int base = 0;
    #pragma unroll
    for (int j = 0; j < 4; j++) base += (j < wid) ? wsum[j] : 0;
    if (t < nb) g_bsumx[t] = base + incl - v;
    if (t == 0) g_off[n] = wsum[0] + wsum[1] + wsum[2] + wsum[3];
}

__global__ __launch_bounds__(1024) void scan_add_kernel(int n) {
    int i = blockIdx.x * 1024 + threadIdx.x;
    if (i < n) {
        int val = g_off[i] + g_bsumx[blockIdx.x];
        g_off[i] = val;
        g_cur[i] = val;
    }
}

__global__ void fill_kernel(const int* __restrict__ ei,
                            const float* __restrict__ ew, int E, int N) {
    int e = blockIdx.x * blockDim.x + threadIdx.x;
    if (e < E) {
        int src = ei[e];
        int dst = ei[E + e];
        if ((unsigned)dst < (unsigned)N && (unsigned)src < (unsigned)N) {
            int pos = atomicAdd(&g_cur[dst], 1);
            g_srcs[pos] = src;
            g_wts[pos]  = ew[e];
        }
    }
}

// One warp per node; 4-deep unrolled fp16 gather (8 B/lane/edge), fp32 accum.
__global__ void aggregate_kernel(int n) {
    int gw   = (blockIdx.x * blockDim.x + threadIdx.x) >> 5;
    int lane = threadIdx.x & 31;
    if (gw >= n) return;
    int i   = g_off[gw];
    int end = g_off[gw + 1];
    float4 a0 = make_float4(0.f, 0.f, 0.f, 0.f);
    float4 a1 = make_float4(0.f, 0.f, 0.f, 0.f);
    float4 a2 = make_float4(0.f, 0.f, 0.f, 0.f);
    float4 a3 = make_float4(0.f, 0.f, 0.f, 0.f);
    for (; i + 4 <= end; i += 4) {
        int   s0 = g_srcs[i],     s1 = g_srcs[i + 1];
        int   s2 = g_srcs[i + 2], s3 = g_srcs[i + 3];
        float w0 = g_wts[i],      w1 = g_wts[i + 1];
        float w2 = g_wts[i + 2],  w3 = g_wts[i + 3];
        uint2 u0 = *((const uint2*)(g_x16 + (size_t)s0 * D) + lane);
        uint2 u1 = *((const uint2*)(g_x16 + (size_t)s1 * D) + lane);
        uint2 u2 = *((const uint2*)(g_x16 + (size_t)s2 * D) + lane);
        uint2 u3 = *((const uint2*)(g_x16 + (size_t)s3 * D) + lane);
        float2 f0a = __half22float2(*(__half2*)&u0.x);
        float2 f0b = __half22float2(*(__half2*)&u0.y);
        float2 f1a = __half22float2(*(__half2*)&u1.x);
        float2 f1b = __half22float2(*(__half2*)&u1.y);
        float2 f2a = __half22float2(*(__half2*)&u2.x);
        float2 f2b = __half22float2(*(__half2*)&u2.y);
        float2 f3a = __half22float2(*(__half2*)&u3.x);
        float2 f3b = __half22float2(*(__half2*)&u3.y);
        a0.x += w0 * f0a.x; a0.y += w0 * f0a.y; a0.z += w0 * f0b.x; a0.w += w0 * f0b.y;
        a1.x += w1 * f1a.x; a1.y += w1 * f1a.y; a1.z += w1 * f1b.x; a1.w += w1 * f1b.y;
        a2.x += w2 * f2a.x; a2.y += w2 * f2a.y; a2.z += w2 * f2b.x; a2.w += w2 * f2b.y;
        a3.x += w3 * f3a.x; a3.y += w3 * f3a.y; a3.z += w3 * f3b.x; a3.w += w3 * f3b.y;
    }
    for (; i < end; i++) {
        int   s = g_srcs[i];
        float w = g_wts[i];
        uint2 u = *((const uint2*)(g_x16 + (size_t)s * D) + lane);
        float2 fa = __half22float2(*(__half2*)&u.x);
        float2 fb = __half22float2(*(__half2*)&u.y);
        a0.x += w * fa.x; a0.y += w * fa.y; a0.z += w * fb.x; a0.w += w * fb.y;
    }
    float4 r = make_float4(a0.x + a1.x + a2.x + a3.x,
                           a0.y + a1.y + a2.y + a3.y,
                           a0.z + a1.z + a2.z + a3.z,
                           a0.w + a1.w + a2.w + a3.w);
    *((float4*)(g_agg + (size_t)gw * D) + lane) = r;
}

// ============================================================================
// SIMT GEMM with packed f32x2 FMAs (identical to round-6 223.7us version).
// ============================================================================

__device__ __forceinline__ ull pack_dup(float a) {
    ull r;
    unsigned int u = __float_as_uint(a);
    asm("mov.b64 %0, {%1, %2};" : "=l"(r) : "r"(u), "r"(u));
    return r;
}

__device__ __forceinline__ void fma_x2(ull& acc, ull a, ull w) {
    asm("fma.rn.f32x2 %0, %1, %2, %0;" : "+l"(acc) : "l"(a), "l"(w));
}

__global__ __launch_bounds__(256) void gemm_kernel(const float* __restrict__ W,
                                                   const float* __restrict__ b,
                                                   float* __restrict__ out, int M) {
    __shared__ __align__(16) float ws[32][132];
    __shared__ __align__(16) float xs[32][132];
    const int tid = threadIdx.x;
    const int tn  = tid & 15;
    const int tm  = tid >> 4;
    const int mb  = blockIdx.x * 128;

    ull acc[8][4];
    #pragma unroll
    for (int i = 0; i < 8; i++)
        #pragma unroll
        for (int j = 0; j < 4; j++) acc[i][j] = 0ULL;

    for (int kb = 0; kb < 128; kb += 32) {
        #pragma unroll
        for (int idx = tid; idx < 128 * 32; idx += 256) {
            int kk = idx & 31, nn = idx >> 5;
            ws[kk][nn] = W[nn * 128 + kb + kk];
        }
        #pragma unroll
        for (int idx = tid; idx < 128 * 32; idx += 256) {
            int kk = idx & 31, mm = idx >> 5;
            int row = mb + mm;
            xs[kk][mm] = (row < M) ? g_agg[(size_t)row * 128 + kb + kk] : 0.f;
        }
        __syncthreads();
        #pragma unroll
        for (int k = 0; k < 32; k++) {
            float4 x0 = *(const float4*)&xs[k][tm * 8];
            float4 x1 = *(const float4*)&xs[k][tm * 8 + 4];
            const ull* wp = (const ull*)&ws[k][tn * 8];
            ull w0 = wp[0], w1 = wp[1], w2 = wp[2], w3 = wp[3];
            float av[8] = {x0.x, x0.y, x0.z, x0.w, x1.x, x1.y, x1.z, x1.w};
            #pragma unroll
            for (int i = 0; i < 8; i++) {
                ull ad = pack_dup(av[i]);
                fma_x2(acc[i][0], ad, w0);
                fma_x2(acc[i][1], ad, w1);
                fma_x2(acc[i][2], ad, w2);
                fma_x2(acc[i][3], ad, w3);
            }
        }
        __syncthreads();
    }

    float bias[8];
    #pragma unroll
    for (int j = 0; j < 8; j++) bias[j] = b[tn * 8 + j];
    #pragma unroll
    for (int i = 0; i < 8; i++) {
        int row = mb + tm * 8 + i;
        if (row < M) {
            float r[8];
            #pragma unroll
            for (int j = 0; j < 4; j++) {
                unsigned int lo, hi;
                asm("mov.b64 {%0, %1}, %2;" : "=r"(lo), "=r"(hi) : "l"(acc[i][j]));
                r[j * 2]     = __uint_as_float(lo);
                r[j * 2 + 1] = __uint_as_float(hi);
            }
            float4 o0 = make_float4(r[0] + bias[0], r[1] + bias[1],
                                    r[2] + bias[2], r[3] + bias[3]);
            float4 o1 = make_float4(r[4] + bias[4], r[5] + bias[5],
                                    r[6] + bias[6], r[7] + bias[7]);
            *(float4*)(out + (size_t)row * 128 + tn * 8)     = o0;
            *(float4*)(out + (size_t)row * 128 + tn * 8 + 4) = o1;
        }
    }
}

// ---------------------------------------------------------------------------
extern "C" void kernel_launch(void* const* d_in, const int* in_sizes, int n_in,
                              void* d_out, int out_size) {
    const float* x  = (const float*)d_in[0];
    const int*   ei = (const int*)d_in[1];     // int32 edge_index [2, E]
    const float* ew = (const float*)d_in[2];
    const float* W  = (const float*)d_in[3];
    const float* b  = (const float*)d_in[4];
    float*       out = (float*)d_out;

    int N = in_sizes[0] / D;      // 100000
    int E = in_sizes[2];          // 1600000
    int nb = (N + 1023) / 1024;   // 98
    int t4 = (N * D) / 4;         // float4 count for convert

    zero_deg_kernel<<<(N + 255) / 256, 256>>>(N);
    convert_x_kernel<<<(t4 + 255) / 256, 256>>>(x, t4);
    count_kernel<<<(E + 255) / 256, 256>>>(ei, E, N);
    scan_blocks_kernel<<<nb, 1024>>>(N);
    scan_bsum_kernel<<<1, 128>>>(nb, N);
    scan_add_kernel<<<nb, 1024>>>(N);
    fill_kernel<<<(E + 255) / 256, 256>>>(ei, ew, E, N);
    aggregate_kernel<<<((size_t)N * 32 + 255) / 256, 256>>>(N);
    gemm_kernel<<<(N + 127) / 128, 256>>>(W, b, out, N);
}

// round 10
// speedup vs baseline: 1.4680x; 1.3432x over previous
#include <cuda_runtime.h>
#include <cuda_fp16.h>
#include <stdint.h>

#define MAX_NODES 100000
#define MAX_EDGES 1600000
#define D 128

typedef unsigned long long ull;

// ---- device scratch ----
__device__ __align__(256) int   g_deg[MAX_NODES];
__device__ __align__(256) int   g_off[MAX_NODES + 1];
__device__ __align__(256) int   g_cur[MAX_NODES];
__device__ __align__(256) int   g_bsum[128];
__device__ __align__(256) int   g_bsumx[128];
__device__ __align__(256) int   g_srcs[MAX_EDGES];
__device__ __align__(256) float g_wts[MAX_EDGES];
__device__ __align__(256) float g_agg[(size_t)MAX_NODES * D];

// ---------------------------------------------------------------------------
__global__ void zero_deg_kernel(int n) {
    int i = blockIdx.x * blockDim.x + threadIdx.x;
    if (i < n) g_deg[i] = 0;
}

__global__ void count_kernel(const int* __restrict__ ei, int E, int N) {
    int e = blockIdx.x * blockDim.x + threadIdx.x;
    if (e < E) {
        int dst = ei[E + e];
        if ((unsigned)dst < (unsigned)N) atomicAdd(&g_deg[dst], 1);
    }
}

__global__ __launch_bounds__(1024) void scan_blocks_kernel(int n) {
    __shared__ int warp_sums[32];
    const int tid  = threadIdx.x;
    const int lane = tid & 31;
    const int wid  = tid >> 5;
    const int i    = blockIdx.x * 1024 + tid;

    int v = (i < n) ? g_deg[i] : 0;
    int incl = v;
    #pragma unroll
    for (int d = 1; d < 32; d <<= 1) {
        int t = __shfl_up_sync(0xFFFFFFFFu, incl, d);
        if (lane >= d) incl += t;
    }
    if (lane == 31) warp_sums[wid] = incl;
    __syncthreads();
    if (wid == 0) {
        int wv = warp_sums[lane];
        #pragma unroll
        for (int d = 1; d < 32; d <<= 1) {
            int t = __shfl_up_sync(0xFFFFFFFFu, wv, d);
            if (lane >= d) wv += t;
        }
        warp_sums[lane] = wv;
    }
    __syncthreads();
    int base = (wid > 0) ? warp_sums[wid - 1] : 0;
    if (i < n) g_off[i] = base + incl - v;
    if (tid == 1023) g_bsum[blockIdx.x] = warp_sums[31];
}

__global__ void scan_bsum_kernel(int nb, int n) {
    __shared__ int wsum[4];
    const int t    = threadIdx.x;
    const int lane = t & 31;
    const int wid  = t >> 5;
    int v = (t < nb) ? g_bsum[t] : 0;
    int incl = v;
    #pragma unroll
    for (int d = 1; d < 32; d <<= 1) {
        int s = __shfl_up_sync(0xFFFFFFFFu, incl, d);
        if (lane >= d) incl += s;
    }
    if (lane == 31) wsum[wid] = incl;
    __syncthreads();
    int base = 0;
    #pragma unroll
    for (int j = 0; j < 4; j++) base += (j < wid) ? wsum[j] : 0;
    if (t < nb) g_bsumx[t] = base + incl - v;
    if (t == 0) g_off[n] = wsum[0] + wsum[1] + wsum[2] + wsum[3];
}

__global__ __launch_bounds__(1024) void scan_add_kernel(int n) {
    int i = blockIdx.x * 1024 + threadIdx.x;
    if (i < n) {
        int val = g_off[i] + g_bsumx[blockIdx.x];
        g_off[i] = val;
        g_cur[i] = val;
    }
}

__global__ void fill_kernel(const int* __restrict__ ei,
                            const float* __restrict__ ew, int E, int N) {
    int e = blockIdx.x * blockDim.x + threadIdx.x;
    if (e < E) {
        int src = ei[e];
        int dst = ei[E + e];
        if ((unsigned)dst < (unsigned)N && (unsigned)src < (unsigned)N) {
            int pos = atomicAdd(&g_cur[dst], 1);
            g_srcs[pos] = src;
            g_wts[pos]  = ew[e];
        }
    }
}

// One warp per node; 4-deep unrolled fp32 gather (round-6 form).
__global__ void aggregate_kernel(const float* __restrict__ x, int n) {
    int gw   = (blockIdx.x * blockDim.x + threadIdx.x) >> 5;
    int lane = threadIdx.x & 31;
    if (gw >= n) return;
    int i   = g_off[gw];
    int end = g_off[gw + 1];
    float4 a0 = make_float4(0.f, 0.f, 0.f, 0.f);
    float4 a1 = make_float4(0.f, 0.f, 0.f, 0.f);
    float4 a2 = make_float4(0.f, 0.f, 0.f, 0.f);
    float4 a3 = make_float4(0.f, 0.f, 0.f, 0.f);
    for (; i + 4 <= end; i += 4) {
        int   s0 = g_srcs[i],     s1 = g_srcs[i + 1];
        int   s2 = g_srcs[i + 2], s3 = g_srcs[i + 3];
        float w0 = g_wts[i],      w1 = g_wts[i + 1];
        float w2 = g_wts[i + 2],  w3 = g_wts[i + 3];
        float4 v0 = *((const float4*)(x + (size_t)s0 * D) + lane);
        float4 v1 = *((const float4*)(x + (size_t)s1 * D) + lane);
        float4 v2 = *((const float4*)(x + (size_t)s2 * D) + lane);
        float4 v3 = *((const float4*)(x + (size_t)s3 * D) + lane);
        a0.x += w0 * v0.x; a0.y += w0 * v0.y; a0.z += w0 * v0.z; a0.w += w0 * v0.w;
        a1.x += w1 * v1.x; a1.y += w1 * v1.y; a1.z += w1 * v1.z; a1.w += w1 * v1.w;
        a2.x += w2 * v2.x; a2.y += w2 * v2.y; a2.z += w2 * v2.z; a2.w += w2 * v2.w;
        a3.x += w3 * v3.x; a3.y += w3 * v3.y; a3.z += w3 * v3.z; a3.w += w3 * v3.w;
    }
    for (; i < end; i++) {
        int   s = g_srcs[i];
        float w = g_wts[i];
        float4 v = *((const float4*)(x + (size_t)s * D) + lane);
        a0.x += w * v.x; a0.y += w * v.y; a0.z += w * v.z; a0.w += w * v.w;
    }
    float4 r = make_float4(a0.x + a1.x + a2.x + a3.x,
                           a0.y + a1.y + a2.y + a3.y,
                           a0.z + a1.z + a2.z + a3.z,
                           a0.w + a1.w + a2.w + a3.w);
    *((float4*)(g_agg + (size_t)gw * D) + lane) = r;
}

// ============================================================================
// HMMA GEMM: out[m][n] = sum_k agg[m][k]*W[n][k] + b[n] via mma.sync
// m16n8k16 f16*f16+f32. CTA 256 thr, tile 128Mx128N, K=128 smem-resident fp16.
// Warp grid 4Mx2N -> warp tile 32x64. W[n][k] row-major IS the col-major B
// fragment layout -> plain ldmatrix, no transpose.
// ============================================================================

#define SH_STRIDE 136   // halfs per row (272B: 16B-aligned, ldmatrix conflict-free)

__device__ __forceinline__ uint32_t smem_u32(const void* p) {
    return (uint32_t)__cvta_generic_to_shared(p);
}

__device__ __forceinline__ void ldsm_x4(uint32_t& r0, uint32_t& r1,
                                        uint32_t& r2, uint32_t& r3, uint32_t a) {
    asm volatile("ldmatrix.sync.aligned.m8n8.x4.shared.b16 {%0,%1,%2,%3}, [%4];"
                 : "=r"(r0), "=r"(r1), "=r"(r2), "=r"(r3) : "r"(a));
}

__device__ __forceinline__ void hmma(float& c0, float& c1, float& c2, float& c3,
                                     uint32_t a0, uint32_t a1, uint32_t a2, uint32_t a3,
                                     uint32_t b0, uint32_t b1) {
    asm volatile("mma.sync.aligned.m16n8k16.row.col.f32.f16.f16.f32 "
                 "{%0,%1,%2,%3}, {%4,%5,%6,%7}, {%8,%9}, {%0,%1,%2,%3};"
                 : "+f"(c0), "+f"(c1), "+f"(c2), "+f"(c3)
                 : "r"(a0), "r"(a1), "r"(a2), "r"(a3), "r"(b0), "r"(b1));
}

#define GEMM_SMEM (2 * 128 * SH_STRIDE * 2)   // bytes

__global__ __launch_bounds__(256) void gemm_hmma_kernel(const float* __restrict__ W,
                                                        const float* __restrict__ b,
                                                        float* __restrict__ out, int M) {
    extern __shared__ __align__(16) __half sh[];
    __half* sA = sh;                       // [128][SH_STRIDE]
    __half* sW = sh + 128 * SH_STRIDE;     // [128][SH_STRIDE]
    const int tid  = threadIdx.x;
    const int wid  = tid >> 5;
    const int lane = tid & 31;
    const int mb   = blockIdx.x * 128;

    // Stage W (fp32 -> fp16), coalesced float4 reads.
    for (int idx = tid; idx < 128 * 32; idx += 256) {
        int r = idx >> 5, c4 = idx & 31;
        float4 v = ((const float4*)(W + r * 128))[c4];
        __half2 h0 = __floats2half2_rn(v.x, v.y);
        __half2 h1 = __floats2half2_rn(v.z, v.w);
        *(__half2*)&sW[r * SH_STRIDE + c4 * 4]     = h0;
        *(__half2*)&sW[r * SH_STRIDE + c4 * 4 + 2] = h1;
    }
    // Stage A tile.
    for (int idx = tid; idx < 128 * 32; idx += 256) {
        int r = idx >> 5, c4 = idx & 31;
        int row = mb + r;
        float4 v = (row < M) ? ((const float4*)(g_agg + (size_t)row * 128))[c4]
                             : make_float4(0.f, 0.f, 0.f, 0.f);
        __half2 h0 = __floats2half2_rn(v.x, v.y);
        __half2 h1 = __floats2half2_rn(v.z, v.w);
        *(__half2*)&sA[r * SH_STRIDE + c4 * 4]     = h0;
        *(__half2*)&sA[r * SH_STRIDE + c4 * 4 + 2] = h1;
    }
    __syncthreads();

    const int m0 = (wid & 3) * 32;   // warp M base
    const int n0 = (wid >> 2) * 64;  // warp N base

    float acc[2][8][4];
    #pragma unroll
    for (int i = 0; i < 2; i++)
        #pragma unroll
        for (int j = 0; j < 8; j++)
            #pragma unroll
            for (int q = 0; q < 4; q++) acc[i][j][q] = 0.f;

    // ldmatrix lane->address components
    const int a_row_off = lane & 15;          // + (lane>>4)*8 cols
    const int a_col_off = (lane >> 4) * 8;
    const int b_row_off = (lane & 7) + ((lane >> 4) & 1) * 8;
    const int b_col_off = ((lane >> 3) & 1) * 8;

    #pragma unroll
    for (int kt = 0; kt < 8; kt++) {
        const int klo = kt * 16;
        uint32_t af[2][4];
        #pragma unroll
        for (int mf = 0; mf < 2; mf++) {
            uint32_t addr = smem_u32(&sA[(m0 + mf * 16 + a_row_off) * SH_STRIDE
                                         + klo + a_col_off]);
            ldsm_x4(af[mf][0], af[mf][1], af[mf][2], af[mf][3], addr);
        }
        uint32_t bf[8][2];
        #pragma unroll
        for (int g = 0; g < 4; g++) {
            uint32_t r0, r1, r2, r3;
            uint32_t addr = smem_u32(&sW[(n0 + g * 16 + b_row_off) * SH_STRIDE
                                         + klo + b_col_off]);
            ldsm_x4(r0, r1, r2, r3, addr);
            bf[g * 2][0] = r0; bf[g * 2][1] = r1;
            bf[g * 2 + 1][0] = r2; bf[g * 2 + 1][1] = r3;
        }
        #pragma unroll
        for (int mf = 0; mf < 2; mf++)
            #pragma unroll
            for (int nf = 0; nf < 8; nf++)
                hmma(acc[mf][nf][0], acc[mf][nf][1], acc[mf][nf][2], acc[mf][nf][3],
                     af[mf][0], af[mf][1], af[mf][2], af[mf][3],
                     bf[nf][0], bf[nf][1]);
    }

    // Epilogue: fp32 + bias, float2 stores.
    const int tq = lane >> 2;       // 0..7 (row-in-frag)
    const int tc = (lane & 3) * 2;  // col pair base
    #pragma unroll
    for (int nf = 0; nf < 8; nf++) {
        int col = n0 + nf * 8 + tc;
        float2 bv = *(const float2*)&b[col];
        #pragma unroll
        for (int mf = 0; mf < 2; mf++) {
            int r0 = mb + m0 + mf * 16 + tq;
            int r1 = r0 + 8;
            if (r0 < M) {
                float2 o = make_float2(acc[mf][nf][0] + bv.x, acc[mf][nf][1] + bv.y);
                *(float2*)&out[(size_t)r0 * 128 + col] = o;
            }
            if (r1 < M) {
                float2 o = make_float2(acc[mf][nf][2] + bv.x, acc[mf][nf][3] + bv.y);
                *(float2*)&out[(size_t)r1 * 128 + col] = o;
            }
        }
    }
}

// ---------------------------------------------------------------------------
extern "C" void kernel_launch(void* const* d_in, const int* in_sizes, int n_in,
                              void* d_out, int out_size) {
    const float* x  = (const float*)d_in[0];
    const int*   ei = (const int*)d_in[1];     // int32 edge_index [2, E]
    const float* ew = (const float*)d_in[2];
    const float* W  = (const float*)d_in[3];
    const float* b  = (const float*)d_in[4];
    float*       out = (float*)d_out;

    int N = in_sizes[0] / D;      // 100000
    int E = in_sizes[2];          // 1600000
    int nb = (N + 1023) / 1024;   // 98

    zero_deg_kernel<<<(N + 255) / 256, 256>>>(N);
    count_kernel<<<(E + 255) / 256, 256>>>(ei, E, N);
    scan_blocks_kernel<<<nb, 1024>>>(N);
    scan_bsum_kernel<<<1, 128>>>(nb, N);
    scan_add_kernel<<<nb, 1024>>>(N);
    fill_kernel<<<(E + 255) / 256, 256>>>(ei, ew, E, N);
    aggregate_kernel<<<((size_t)N * 32 + 255) / 256, 256>>>(x, N);

    cudaFuncSetAttribute(gemm_hmma_kernel,
                         cudaFuncAttributeMaxDynamicSharedMemorySize, GEMM_SMEM);
    gemm_hmma_kernel<<<(N + 127) / 128, 256, GEMM_SMEM>>>(W, b, out, N);
}